// round 3
// baseline (speedup 1.0000x reference)
#include <cuda_runtime.h>
#include <math.h>

// Problem constants (fixed by the reference)
#define N_NODES 50000
#define N_EDGES 800000
#define IN_F    64
#define HEADS   8
#define HID     32
#define CH      256          // HEADS*HID
#define NEG     0.2f

// ---------------- scratch (no cudaMalloc allowed) ----------------
__device__ float g_feat1[(size_t)N_NODES * CH];   // 51.2 MB
__device__ float g_el1[N_NODES * HEADS];
__device__ float g_er1[N_NODES * HEADS];
__device__ float g_feat2[N_NODES];                // layer-2 per-node scalar feature
__device__ int   g_deg[N_NODES];
__device__ int   g_off[N_NODES];
__device__ int   g_cur[N_NODES];
__device__ int   g_csr_src[N_EDGES];

// ---------------- CSR construction ----------------
__global__ void k_zero_deg() {
    int i = blockIdx.x * blockDim.x + threadIdx.x;
    if (i < N_NODES) g_deg[i] = 0;
}

__global__ void k_count(const int* __restrict__ dst) {
    int e = blockIdx.x * blockDim.x + threadIdx.x;
    if (e < N_EDGES) atomicAdd(&g_deg[dst[e]], 1);
}

// single-block exclusive scan over 50000 degrees -> offsets + cursor copy
__global__ void k_scan() {
    __shared__ int sums[1024];
    const int t = threadIdx.x;
    const int chunk = (N_NODES + 1023) / 1024;
    int begin = t * chunk;
    int end   = begin + chunk; if (end > N_NODES) end = N_NODES;
    int s = 0;
    for (int i = begin; i < end; ++i) s += g_deg[i];
    sums[t] = s;
    __syncthreads();
    // Hillis-Steele inclusive scan
    for (int ofs = 1; ofs < 1024; ofs <<= 1) {
        int v = (t >= ofs) ? sums[t - ofs] : 0;
        __syncthreads();
        sums[t] += v;
        __syncthreads();
    }
    int run = (t == 0) ? 0 : sums[t - 1];
    for (int i = begin; i < end; ++i) {
        g_off[i] = run;
        g_cur[i] = run;
        run += g_deg[i];
    }
}

__global__ void k_fill(const int* __restrict__ src, const int* __restrict__ dst) {
    int e = blockIdx.x * blockDim.x + threadIdx.x;
    if (e >= N_EDGES) return;
    int d = dst[e];
    int pos = atomicAdd(&g_cur[d], 1);
    g_csr_src[pos] = src[e];
}

// ---------------- layer 1 GEMM: feat1 = X @ W1  (50000x64 * 64x256) ----------
// block = 256 threads (one output column each), 16 nodes per block
__global__ void k_gemm(const float* __restrict__ x, const float* __restrict__ W) {
    __shared__ float xs[16][IN_F];
    const int tid = threadIdx.x;
    const int n0 = blockIdx.x * 16;
    #pragma unroll
    for (int r = 0; r < 4; ++r) {
        int e = tid + r * 256;
        int n = e >> 6, i = e & 63;
        int node = n0 + n;
        xs[n][i] = (node < N_NODES) ? x[node * IN_F + i] : 0.f;
    }
    __syncthreads();
    float acc[16];
    #pragma unroll
    for (int n = 0; n < 16; ++n) acc[n] = 0.f;
    const int c = tid;
    #pragma unroll 4
    for (int i = 0; i < IN_F; ++i) {
        float w = W[i * CH + c];
        #pragma unroll
        for (int n = 0; n < 16; ++n) acc[n] = fmaf(xs[n][i], w, acc[n]);
    }
    #pragma unroll
    for (int n = 0; n < 16; ++n) {
        int node = n0 + n;
        if (node < N_NODES) g_feat1[(size_t)node * CH + c] = acc[n];
    }
}

// ---------------- per-node attention logits el/er (warp per node) ------------
__global__ void k_eler(const float* __restrict__ al, const float* __restrict__ ar) {
    const int warp = threadIdx.x >> 5, l = threadIdx.x & 31;
    const int n = blockIdx.x * 8 + warp;
    if (n >= N_NODES) return;
    const float* f = g_feat1 + (size_t)n * CH;
    float pl[8], pr[8];
    #pragma unroll
    for (int k = 0; k < 8; ++k) {
        float v = f[k * 32 + l];
        pl[k] = v * al[k * 32 + l];
        pr[k] = v * ar[k * 32 + l];
    }
    #pragma unroll
    for (int o = 16; o; o >>= 1) {
        #pragma unroll
        for (int k = 0; k < 8; ++k) {
            pl[k] += __shfl_xor_sync(0xffffffffu, pl[k], o);
            pr[k] += __shfl_xor_sync(0xffffffffu, pr[k], o);
        }
    }
    if (l == 0) {
        #pragma unroll
        for (int k = 0; k < 8; ++k) {
            g_el1[n * 8 + k] = pl[k];
            g_er1[n * 8 + k] = pr[k];
        }
    }
}

// ---------------- layer-1 aggregation (warp per dst, online softmax) ---------
// lane l owns channels [l*8, l*8+8)  ->  head = l/4
// epilogue fuses +b1, ReLU, and the layer-2 linear h . W2 -> g_feat2[n]
__global__ void k_agg1(const float* __restrict__ b1, const float* __restrict__ W2) {
    const int warp = threadIdx.x >> 5, l = threadIdx.x & 31;
    const int n = blockIdx.x * 8 + warp;
    if (n >= N_NODES) return;
    const int h = l >> 2;
    const float er = g_er1[n * 8 + h];
    const int start = g_off[n], cnt = g_deg[n];
    float m = -3.0e38f, s = 0.f;
    float acc[8];
    #pragma unroll
    for (int i = 0; i < 8; ++i) acc[i] = 0.f;
    for (int k = 0; k < cnt; ++k) {
        int sn = g_csr_src[start + k];
        float e = g_el1[sn * 8 + h] + er;
        e = (e > 0.f) ? e : NEG * e;           // leaky relu
        float mn = fmaxf(m, e);
        float sc = __expf(m - mn);
        float p  = __expf(e - mn);
        s = s * sc + p;
        const float4* fp = (const float4*)(g_feat1 + (size_t)sn * CH + l * 8);
        float4 a = fp[0], b = fp[1];
        acc[0] = fmaf(p, a.x, acc[0] * sc);
        acc[1] = fmaf(p, a.y, acc[1] * sc);
        acc[2] = fmaf(p, a.z, acc[2] * sc);
        acc[3] = fmaf(p, a.w, acc[3] * sc);
        acc[4] = fmaf(p, b.x, acc[4] * sc);
        acc[5] = fmaf(p, b.y, acc[5] * sc);
        acc[6] = fmaf(p, b.z, acc[6] * sc);
        acc[7] = fmaf(p, b.w, acc[7] * sc);
        m = mn;
    }
    float inv = (cnt > 0) ? 1.f / s : 0.f;
    float dot = 0.f;
    #pragma unroll
    for (int i = 0; i < 8; ++i) {
        float v = acc[i] * inv + b1[l * 8 + i];
        v = fmaxf(v, 0.f);                      // ReLU
        dot = fmaf(v, W2[l * 8 + i], dot);      // layer-2 linear (256 -> 1)
    }
    #pragma unroll
    for (int o = 16; o; o >>= 1) dot += __shfl_xor_sync(0xffffffffu, dot, o);
    if (l == 0) g_feat2[n] = dot;
}

// ---------------- layer-2 aggregation + sigmoid (thread per dst) -------------
__global__ void k_gat2(const float* __restrict__ al2p, const float* __restrict__ ar2p,
                       const float* __restrict__ b2p, float* __restrict__ out) {
    int n = blockIdx.x * blockDim.x + threadIdx.x;
    if (n >= N_NODES) return;
    const float al2 = al2p[0], ar2 = ar2p[0], b2 = b2p[0];
    const float er = g_feat2[n] * ar2;
    const int start = g_off[n], cnt = g_deg[n];
    float m = -3.0e38f, s = 0.f, acc = 0.f;
    for (int k = 0; k < cnt; ++k) {
        float fs = g_feat2[g_csr_src[start + k]];
        float e = fs * al2 + er;
        e = (e > 0.f) ? e : NEG * e;
        float mn = fmaxf(m, e);
        float sc = __expf(m - mn);
        float p  = __expf(e - mn);
        s = s * sc + p;
        acc = fmaf(p, fs, acc * sc);
        m = mn;
    }
    float r = (cnt > 0) ? (acc / s + b2) : b2;
    out[n] = 1.f / (1.f + __expf(-r));
}

// ---------------- launch ----------------
extern "C" void kernel_launch(void* const* d_in, const int* in_sizes, int n_in,
                              void* d_out, int out_size) {
    const float* x    = (const float*)d_in[0];   // [N,64]
    const int*   src  = (const int*)  d_in[1];   // [E]
    const int*   dst  = (const int*)  d_in[2];   // [E]
    // d_in[3] edge_types: unused
    const float* W1   = (const float*)d_in[4];   // [64,8,32]
    const float* al1  = (const float*)d_in[5];   // [8,32]
    const float* ar1  = (const float*)d_in[6];   // [8,32]
    const float* b1   = (const float*)d_in[7];   // [8,32]
    const float* W2   = (const float*)d_in[8];   // [256,1,1]
    const float* al2  = (const float*)d_in[9];   // [1,1]
    const float* ar2  = (const float*)d_in[10];  // [1,1]
    const float* b2   = (const float*)d_in[11];  // [1,1]
    float* out = (float*)d_out;                  // [N,1]

    (void)in_sizes; (void)n_in; (void)out_size;

    // CSR build
    k_zero_deg<<<(N_NODES + 255) / 256, 256>>>();
    k_count<<<(N_EDGES + 255) / 256, 256>>>(dst);
    k_scan<<<1, 1024>>>();
    k_fill<<<(N_EDGES + 255) / 256, 256>>>(src, dst);

    // layer 1
    k_gemm<<<(N_NODES + 15) / 16, 256>>>(x, W1);
    k_eler<<<(N_NODES + 7) / 8, 256>>>(al1, ar1);
    k_agg1<<<(N_NODES + 7) / 8, 256>>>(b1, W2);

    // layer 2
    k_gat2<<<(N_NODES + 255) / 256, 256>>>(al2, ar2, b2, out);
}

// round 4
// speedup vs baseline: 1.0845x; 1.0845x over previous
#include <cuda_runtime.h>
#include <cuda_fp16.h>
#include <math.h>

// Problem constants (fixed by the reference)
#define N_NODES 50000
#define N_EDGES 800000
#define IN_F    64
#define HEADS   8
#define HID     32
#define CH      256          // HEADS*HID
#define NEG     0.2f

// ---------------- scratch (no cudaMalloc allowed) ----------------
__device__ __align__(16) __half g_feat1h[(size_t)N_NODES * CH];  // 25.6 MB fp16 gather table
__device__ float g_el1[N_NODES * HEADS];
__device__ float g_er1[N_NODES * HEADS];
__device__ float g_feat2[N_NODES];                // layer-2 per-node scalar feature
__device__ int   g_deg[N_NODES];
__device__ int   g_off[N_NODES];
__device__ int   g_cur[N_NODES];
__device__ int   g_csr_src[N_EDGES];

// ---------------- CSR construction ----------------
__global__ void k_zero_deg() {
    int i = blockIdx.x * blockDim.x + threadIdx.x;
    if (i < N_NODES) g_deg[i] = 0;
}

__global__ void k_count(const int* __restrict__ dst) {
    int i = (blockIdx.x * blockDim.x + threadIdx.x) * 4;
    if (i + 3 < N_EDGES) {
        int4 d = *(const int4*)(dst + i);
        atomicAdd(&g_deg[d.x], 1);
        atomicAdd(&g_deg[d.y], 1);
        atomicAdd(&g_deg[d.z], 1);
        atomicAdd(&g_deg[d.w], 1);
    } else {
        for (int e = i; e < N_EDGES; ++e) atomicAdd(&g_deg[dst[e]], 1);
    }
}

// single-block exclusive scan over 50000 degrees -> offsets + cursor copy
__global__ void k_scan() {
    __shared__ int sums[1024];
    const int t = threadIdx.x;
    const int chunk = (N_NODES + 1023) / 1024;
    int begin = t * chunk;
    int end   = begin + chunk; if (end > N_NODES) end = N_NODES;
    int s = 0;
    for (int i = begin; i < end; ++i) s += g_deg[i];
    sums[t] = s;
    __syncthreads();
    for (int ofs = 1; ofs < 1024; ofs <<= 1) {
        int v = (t >= ofs) ? sums[t - ofs] : 0;
        __syncthreads();
        sums[t] += v;
        __syncthreads();
    }
    int run = (t == 0) ? 0 : sums[t - 1];
    for (int i = begin; i < end; ++i) {
        g_off[i] = run;
        g_cur[i] = run;
        run += g_deg[i];
    }
}

__global__ void k_fill(const int* __restrict__ src, const int* __restrict__ dst) {
    int i = (blockIdx.x * blockDim.x + threadIdx.x) * 4;
    if (i + 3 < N_EDGES) {
        int4 d = *(const int4*)(dst + i);
        int4 s = *(const int4*)(src + i);
        g_csr_src[atomicAdd(&g_cur[d.x], 1)] = s.x;
        g_csr_src[atomicAdd(&g_cur[d.y], 1)] = s.y;
        g_csr_src[atomicAdd(&g_cur[d.z], 1)] = s.z;
        g_csr_src[atomicAdd(&g_cur[d.w], 1)] = s.w;
    } else {
        for (int e = i; e < N_EDGES; ++e)
            g_csr_src[atomicAdd(&g_cur[dst[e]], 1)] = src[e];
    }
}

// ---------------- layer-1 GEMM + fused el/er ---------------------------------
// block = 256 threads (one output channel each), 16 nodes per block.
// warp w covers channels [32w, 32w+32) == head w  ->  warp-reduce gives el/er.
__global__ void k_gemm(const float* __restrict__ x, const float* __restrict__ W,
                       const float* __restrict__ al, const float* __restrict__ ar) {
    __shared__ float xs[16][IN_F];
    const int tid = threadIdx.x;
    const int n0 = blockIdx.x * 16;
    #pragma unroll
    for (int r = 0; r < 4; ++r) {
        int e = tid + r * 256;
        int n = e >> 6, i = e & 63;
        int node = n0 + n;
        xs[n][i] = (node < N_NODES) ? x[node * IN_F + i] : 0.f;
    }
    __syncthreads();
    float acc[16];
    #pragma unroll
    for (int n = 0; n < 16; ++n) acc[n] = 0.f;
    const int c = tid;
    #pragma unroll 4
    for (int i = 0; i < IN_F; ++i) {
        float w = W[i * CH + c];
        #pragma unroll
        for (int n = 0; n < 16; ++n) acc[n] = fmaf(xs[n][i], w, acc[n]);
    }
    // write fp16 feature table (coalesced: 256 consecutive halves per node)
    #pragma unroll
    for (int n = 0; n < 16; ++n) {
        int node = n0 + n;
        if (node < N_NODES) g_feat1h[(size_t)node * CH + c] = __float2half_rn(acc[n]);
    }
    // fused el/er: warp-reduce acc*al, acc*ar over this head's 32 channels
    const float alc = al[c], arc = ar[c];
    const int head = c >> 5, lane = c & 31;
    #pragma unroll
    for (int n = 0; n < 16; ++n) {
        float pl = acc[n] * alc;
        float pr = acc[n] * arc;
        #pragma unroll
        for (int o = 16; o; o >>= 1) {
            pl += __shfl_xor_sync(0xffffffffu, pl, o);
            pr += __shfl_xor_sync(0xffffffffu, pr, o);
        }
        if (lane == 0) {
            int node = n0 + n;
            if (node < N_NODES) {
                g_el1[node * 8 + head] = pl;
                g_er1[node * 8 + head] = pr;
            }
        }
    }
}

// ---------------- layer-1 aggregation (warp per dst, two-pass softmax) -------
// lane l owns channels [l*8, l*8+8)  ->  head = l/4
// epilogue fuses +b1, ReLU, and the layer-2 linear h . W2 -> g_feat2[n]
__global__ void k_agg1(const float* __restrict__ b1, const float* __restrict__ W2) {
    const int warp = threadIdx.x >> 5, l = threadIdx.x & 31;
    const int n = blockIdx.x * 8 + warp;
    if (n >= N_NODES) return;
    const int h = l >> 2;
    const float er = g_er1[n * 8 + h];
    const int start = g_off[n], cnt = g_deg[n];

    // pass 1: row max of leaky-relu logits (cheap: 36 B/edge, no exp chain)
    float m = -3.0e38f;
    for (int k = 0; k < cnt; ++k) {
        int sn = g_csr_src[start + k];
        float e = g_el1[sn * 8 + h] + er;
        e = (e > 0.f) ? e : NEG * e;
        m = fmaxf(m, e);
    }

    // pass 2: exp weights + fp16 feature gather-accumulate (no rescale chain)
    float s = 0.f;
    float acc[8];
    #pragma unroll
    for (int i = 0; i < 8; ++i) acc[i] = 0.f;

    int sn = (cnt > 0) ? g_csr_src[start] : 0;
    for (int k = 0; k < cnt; ++k) {
        int sn_next = (k + 1 < cnt) ? g_csr_src[start + k + 1] : 0;
        float e = g_el1[sn * 8 + h] + er;
        e = (e > 0.f) ? e : NEG * e;
        float p = __expf(e - m);
        s += p;
        uint4 raw = *reinterpret_cast<const uint4*>(g_feat1h + (size_t)sn * CH + (l << 3));
        float2 f0 = __half22float2(*reinterpret_cast<__half2*>(&raw.x));
        float2 f1 = __half22float2(*reinterpret_cast<__half2*>(&raw.y));
        float2 f2 = __half22float2(*reinterpret_cast<__half2*>(&raw.z));
        float2 f3 = __half22float2(*reinterpret_cast<__half2*>(&raw.w));
        acc[0] = fmaf(p, f0.x, acc[0]);
        acc[1] = fmaf(p, f0.y, acc[1]);
        acc[2] = fmaf(p, f1.x, acc[2]);
        acc[3] = fmaf(p, f1.y, acc[3]);
        acc[4] = fmaf(p, f2.x, acc[4]);
        acc[5] = fmaf(p, f2.y, acc[5]);
        acc[6] = fmaf(p, f3.x, acc[6]);
        acc[7] = fmaf(p, f3.y, acc[7]);
        sn = sn_next;
    }

    float inv = (cnt > 0) ? 1.f / s : 0.f;
    float dot = 0.f;
    #pragma unroll
    for (int i = 0; i < 8; ++i) {
        float v = acc[i] * inv + b1[l * 8 + i];
        v = fmaxf(v, 0.f);                      // ReLU
        dot = fmaf(v, W2[l * 8 + i], dot);      // layer-2 linear (256 -> 1)
    }
    #pragma unroll
    for (int o = 16; o; o >>= 1) dot += __shfl_xor_sync(0xffffffffu, dot, o);
    if (l == 0) g_feat2[n] = dot;
}

// ---------------- layer-2 aggregation + sigmoid (thread per dst) -------------
__global__ void k_gat2(const float* __restrict__ al2p, const float* __restrict__ ar2p,
                       const float* __restrict__ b2p, float* __restrict__ out) {
    int n = blockIdx.x * blockDim.x + threadIdx.x;
    if (n >= N_NODES) return;
    const float al2 = al2p[0], ar2 = ar2p[0], b2 = b2p[0];
    const float er = g_feat2[n] * ar2;
    const int start = g_off[n], cnt = g_deg[n];
    float m = -3.0e38f, s = 0.f, acc = 0.f;
    for (int k = 0; k < cnt; ++k) {
        float fs = g_feat2[g_csr_src[start + k]];
        float e = fs * al2 + er;
        e = (e > 0.f) ? e : NEG * e;
        float mn = fmaxf(m, e);
        float sc = __expf(m - mn);
        float p  = __expf(e - mn);
        s = s * sc + p;
        acc = fmaf(p, fs, acc * sc);
        m = mn;
    }
    float r = (cnt > 0) ? (acc / s + b2) : b2;
    out[n] = 1.f / (1.f + __expf(-r));
}

// ---------------- launch ----------------
extern "C" void kernel_launch(void* const* d_in, const int* in_sizes, int n_in,
                              void* d_out, int out_size) {
    const float* x    = (const float*)d_in[0];   // [N,64]
    const int*   src  = (const int*)  d_in[1];   // [E]
    const int*   dst  = (const int*)  d_in[2];   // [E]
    // d_in[3] edge_types: unused
    const float* W1   = (const float*)d_in[4];   // [64,8,32]
    const float* al1  = (const float*)d_in[5];   // [8,32]
    const float* ar1  = (const float*)d_in[6];   // [8,32]
    const float* b1   = (const float*)d_in[7];   // [8,32]
    const float* W2   = (const float*)d_in[8];   // [256,1,1]
    const float* al2  = (const float*)d_in[9];   // [1,1]
    const float* ar2  = (const float*)d_in[10];  // [1,1]
    const float* b2   = (const float*)d_in[11];  // [1,1]
    float* out = (float*)d_out;                  // [N,1]

    (void)in_sizes; (void)n_in; (void)out_size;

    // CSR build
    k_zero_deg<<<(N_NODES + 255) / 256, 256>>>();
    k_count<<<(N_EDGES / 4 + 255) / 256, 256>>>(dst);
    k_scan<<<1, 1024>>>();
    k_fill<<<(N_EDGES / 4 + 255) / 256, 256>>>(src, dst);

    // layer 1 (GEMM fused with el/er)
    k_gemm<<<(N_NODES + 15) / 16, 256>>>(x, W1, al1, ar1);
    k_agg1<<<(N_NODES + 7) / 8, 256>>>(b1, W2);

    // layer 2
    k_gat2<<<(N_NODES + 255) / 256, 256>>>(al2, ar2, b2, out);
}

// round 6
// speedup vs baseline: 1.2102x; 1.1159x over previous
#include <cuda_runtime.h>
#include <cuda_fp16.h>
#include <math.h>

// Problem constants (fixed by the reference)
#define N_NODES 50000
#define N_EDGES 800000
#define IN_F    64
#define HEADS   8
#define HID     32
#define CH      256          // HEADS*HID
#define NEG     0.2f

// ---------------- scratch (no cudaMalloc allowed) ----------------
__device__ __align__(16) __half g_feat1h[(size_t)N_NODES * CH];  // 25.6 MB fp16 gather table
__device__ float g_el1[N_NODES * HEADS];
__device__ float g_er1[N_NODES * HEADS];
__device__ float g_feat2[N_NODES];                // layer-2 per-node scalar feature
__device__ int   g_deg[N_NODES];
__device__ int   g_off[N_NODES];
__device__ int   g_cur[N_NODES];
__device__ int   g_csr_src[N_EDGES];

// ---------------- CSR construction ----------------
__global__ void k_zero_deg() {
    int i = blockIdx.x * blockDim.x + threadIdx.x;
    if (i < N_NODES) g_deg[i] = 0;
}

__global__ void k_count(const int* __restrict__ dst) {
    int i = (blockIdx.x * blockDim.x + threadIdx.x) * 4;
    if (i + 3 < N_EDGES) {
        int4 d = *(const int4*)(dst + i);
        atomicAdd(&g_deg[d.x], 1);
        atomicAdd(&g_deg[d.y], 1);
        atomicAdd(&g_deg[d.z], 1);
        atomicAdd(&g_deg[d.w], 1);
    } else {
        for (int e = i; e < N_EDGES; ++e) atomicAdd(&g_deg[dst[e]], 1);
    }
}

// single-block exclusive scan over 50000 degrees -> offsets + cursor copy
__global__ void k_scan() {
    __shared__ int sums[1024];
    const int t = threadIdx.x;
    const int chunk = (N_NODES + 1023) / 1024;
    int begin = t * chunk;
    int end   = begin + chunk; if (end > N_NODES) end = N_NODES;
    int s = 0;
    for (int i = begin; i < end; ++i) s += g_deg[i];
    sums[t] = s;
    __syncthreads();
    for (int ofs = 1; ofs < 1024; ofs <<= 1) {
        int v = (t >= ofs) ? sums[t - ofs] : 0;
        __syncthreads();
        sums[t] += v;
        __syncthreads();
    }
    int run = (t == 0) ? 0 : sums[t - 1];
    for (int i = begin; i < end; ++i) {
        g_off[i] = run;
        g_cur[i] = run;
        run += g_deg[i];
    }
}

__global__ void k_fill(const int* __restrict__ src, const int* __restrict__ dst) {
    int i = (blockIdx.x * blockDim.x + threadIdx.x) * 4;
    if (i + 3 < N_EDGES) {
        int4 d = *(const int4*)(dst + i);
        int4 s = *(const int4*)(src + i);
        g_csr_src[atomicAdd(&g_cur[d.x], 1)] = s.x;
        g_csr_src[atomicAdd(&g_cur[d.y], 1)] = s.y;
        g_csr_src[atomicAdd(&g_cur[d.z], 1)] = s.z;
        g_csr_src[atomicAdd(&g_cur[d.w], 1)] = s.w;
    } else {
        for (int e = i; e < N_EDGES; ++e)
            g_csr_src[atomicAdd(&g_cur[dst[e]], 1)] = src[e];
    }
}

// ---------------- layer-1 GEMM + fused el/er ---------------------------------
// block = 256 threads (one output channel each), 16 nodes per block.
// warp w covers channels [32w, 32w+32) == head w  ->  warp-reduce gives el/er.
__global__ void k_gemm(const float* __restrict__ x, const float* __restrict__ W,
                       const float* __restrict__ al, const float* __restrict__ ar) {
    __shared__ float xs[16][IN_F];
    const int tid = threadIdx.x;
    const int n0 = blockIdx.x * 16;
    #pragma unroll
    for (int r = 0; r < 4; ++r) {
        int e = tid + r * 256;
        int n = e >> 6, i = e & 63;
        int node = n0 + n;
        xs[n][i] = (node < N_NODES) ? x[node * IN_F + i] : 0.f;
    }
    __syncthreads();
    float acc[16];
    #pragma unroll
    for (int n = 0; n < 16; ++n) acc[n] = 0.f;
    const int c = tid;
    #pragma unroll 4
    for (int i = 0; i < IN_F; ++i) {
        float w = W[i * CH + c];
        #pragma unroll
        for (int n = 0; n < 16; ++n) acc[n] = fmaf(xs[n][i], w, acc[n]);
    }
    // write fp16 feature table (coalesced: 256 consecutive halves per node)
    #pragma unroll
    for (int n = 0; n < 16; ++n) {
        int node = n0 + n;
        if (node < N_NODES) g_feat1h[(size_t)node * CH + c] = __float2half_rn(acc[n]);
    }
    // fused el/er: warp-reduce acc*al, acc*ar over this head's 32 channels
    const float alc = al[c], arc = ar[c];
    const int head = c >> 5, lane = c & 31;
    #pragma unroll
    for (int n = 0; n < 16; ++n) {
        float pl = acc[n] * alc;
        float pr = acc[n] * arc;
        #pragma unroll
        for (int o = 16; o; o >>= 1) {
            pl += __shfl_xor_sync(0xffffffffu, pl, o);
            pr += __shfl_xor_sync(0xffffffffu, pr, o);
        }
        if (lane == 0) {
            int node = n0 + n;
            if (node < N_NODES) {
                g_el1[node * 8 + head] = pl;
                g_er1[node * 8 + head] = pr;
            }
        }
    }
}

// ---------------- layer-1 aggregation (warp per dst, SINGLE pass) ------------
// No max-subtraction: softmax is shift-invariant and logits here are bounded
// (|logit| << 80), so exp() cannot overflow. One pass, 4 edges per step for MLP.
// lane l owns channels [l*8, l*8+8)  ->  head = l/4
// epilogue fuses +b1, ReLU, and the layer-2 linear h . W2 -> g_feat2[n]
__global__ void k_agg1(const float* __restrict__ b1, const float* __restrict__ W2) {
    const int warp = threadIdx.x >> 5, l = threadIdx.x & 31;
    const int n = blockIdx.x * 8 + warp;
    if (n >= N_NODES) return;
    const int h = l >> 2;
    const float er = g_er1[n * 8 + h];
    const int start = g_off[n], cnt = g_deg[n];

    float s = 0.f;
    float acc[8];
    #pragma unroll
    for (int i = 0; i < 8; ++i) acc[i] = 0.f;

    const int co = l << 3;   // channel offset for this lane
    int k = 0;
    for (; k + 4 <= cnt; k += 4) {
        // 4 independent index loads (uniform addresses, issued back-to-back)
        int sn[4];
        #pragma unroll
        for (int j = 0; j < 4; ++j) sn[j] = g_csr_src[start + k + j];
        // 4 independent logit gathers
        float e[4];
        #pragma unroll
        for (int j = 0; j < 4; ++j) e[j] = g_el1[sn[j] * 8 + h] + er;
        // 4 independent 16B feature-row loads
        uint4 r[4];
        #pragma unroll
        for (int j = 0; j < 4; ++j)
            r[j] = *reinterpret_cast<const uint4*>(g_feat1h + (size_t)sn[j] * CH + co);
        float p[4];
        #pragma unroll
        for (int j = 0; j < 4; ++j) {
            float ej = e[j];
            ej = (ej > 0.f) ? ej : NEG * ej;
            p[j] = __expf(ej);
        }
        s += (p[0] + p[1]) + (p[2] + p[3]);
        #pragma unroll
        for (int j = 0; j < 4; ++j) {
            float2 f0 = __half22float2(*reinterpret_cast<__half2*>(&r[j].x));
            float2 f1 = __half22float2(*reinterpret_cast<__half2*>(&r[j].y));
            float2 f2 = __half22float2(*reinterpret_cast<__half2*>(&r[j].z));
            float2 f3 = __half22float2(*reinterpret_cast<__half2*>(&r[j].w));
            acc[0] = fmaf(p[j], f0.x, acc[0]);
            acc[1] = fmaf(p[j], f0.y, acc[1]);
            acc[2] = fmaf(p[j], f1.x, acc[2]);
            acc[3] = fmaf(p[j], f1.y, acc[3]);
            acc[4] = fmaf(p[j], f2.x, acc[4]);
            acc[5] = fmaf(p[j], f2.y, acc[5]);
            acc[6] = fmaf(p[j], f3.x, acc[6]);
            acc[7] = fmaf(p[j], f3.y, acc[7]);
        }
    }
    for (; k < cnt; ++k) {
        int sn = g_csr_src[start + k];
        float e = g_el1[sn * 8 + h] + er;
        e = (e > 0.f) ? e : NEG * e;
        float p = __expf(e);
        s += p;
        uint4 rr = *reinterpret_cast<const uint4*>(g_feat1h + (size_t)sn * CH + co);
        float2 f0 = __half22float2(*reinterpret_cast<__half2*>(&rr.x));
        float2 f1 = __half22float2(*reinterpret_cast<__half2*>(&rr.y));
        float2 f2 = __half22float2(*reinterpret_cast<__half2*>(&rr.z));
        float2 f3 = __half22float2(*reinterpret_cast<__half2*>(&rr.w));
        acc[0] = fmaf(p, f0.x, acc[0]);
        acc[1] = fmaf(p, f0.y, acc[1]);
        acc[2] = fmaf(p, f1.x, acc[2]);
        acc[3] = fmaf(p, f1.y, acc[3]);
        acc[4] = fmaf(p, f2.x, acc[4]);
        acc[5] = fmaf(p, f2.y, acc[5]);
        acc[6] = fmaf(p, f3.x, acc[6]);
        acc[7] = fmaf(p, f3.y, acc[7]);
    }

    // epilogue: coalesced 32B loads of b1/W2 slices for this lane
    float4 bv0 = *reinterpret_cast<const float4*>(b1 + co);
    float4 bv1 = *reinterpret_cast<const float4*>(b1 + co + 4);
    float4 wv0 = *reinterpret_cast<const float4*>(W2 + co);
    float4 wv1 = *reinterpret_cast<const float4*>(W2 + co + 4);
    const float bb[8] = {bv0.x, bv0.y, bv0.z, bv0.w, bv1.x, bv1.y, bv1.z, bv1.w};
    const float ww[8] = {wv0.x, wv0.y, wv0.z, wv0.w, wv1.x, wv1.y, wv1.z, wv1.w};
    float inv = (cnt > 0) ? 1.f / s : 0.f;
    float dot = 0.f;
    #pragma unroll
    for (int i = 0; i < 8; ++i) {
        float v = acc[i] * inv + bb[i];
        v = fmaxf(v, 0.f);                      // ReLU
        dot = fmaf(v, ww[i], dot);              // layer-2 linear (256 -> 1)
    }
    #pragma unroll
    for (int o = 16; o; o >>= 1) dot += __shfl_xor_sync(0xffffffffu, dot, o);
    if (l == 0) g_feat2[n] = dot;
}

// ---------------- layer-2 aggregation + sigmoid (thread per dst, 1 pass) -----
__global__ void k_gat2(const float* __restrict__ al2p, const float* __restrict__ ar2p,
                       const float* __restrict__ b2p, float* __restrict__ out) {
    int n = blockIdx.x * blockDim.x + threadIdx.x;
    if (n >= N_NODES) return;
    const float al2 = al2p[0], ar2 = ar2p[0], b2 = b2p[0];
    const float er = g_feat2[n] * ar2;
    const int start = g_off[n], cnt = g_deg[n];
    float s = 0.f, acc = 0.f;
    int k = 0;
    for (; k + 4 <= cnt; k += 4) {
        int s0 = g_csr_src[start + k + 0];
        int s1 = g_csr_src[start + k + 1];
        int s2 = g_csr_src[start + k + 2];
        int s3 = g_csr_src[start + k + 3];
        float f0 = g_feat2[s0], f1 = g_feat2[s1], f2 = g_feat2[s2], f3 = g_feat2[s3];
        float e0 = f0 * al2 + er, e1 = f1 * al2 + er, e2 = f2 * al2 + er, e3 = f3 * al2 + er;
        e0 = (e0 > 0.f) ? e0 : NEG * e0;
        e1 = (e1 > 0.f) ? e1 : NEG * e1;
        e2 = (e2 > 0.f) ? e2 : NEG * e2;
        e3 = (e3 > 0.f) ? e3 : NEG * e3;
        float p0 = __expf(e0), p1 = __expf(e1), p2 = __expf(e2), p3 = __expf(e3);
        s += (p0 + p1) + (p2 + p3);
        acc = fmaf(p0, f0, acc);
        acc = fmaf(p1, f1, acc);
        acc = fmaf(p2, f2, acc);
        acc = fmaf(p3, f3, acc);
    }
    for (; k < cnt; ++k) {
        float fs = g_feat2[g_csr_src[start + k]];
        float e = fs * al2 + er;
        e = (e > 0.f) ? e : NEG * e;
        float p = __expf(e);
        s += p;
        acc = fmaf(p, fs, acc);
    }
    float r = (cnt > 0) ? (acc / s + b2) : b2;
    out[n] = 1.f / (1.f + __expf(-r));
}

// ---------------- launch ----------------
extern "C" void kernel_launch(void* const* d_in, const int* in_sizes, int n_in,
                              void* d_out, int out_size) {
    const float* x    = (const float*)d_in[0];   // [N,64]
    const int*   src  = (const int*)  d_in[1];   // [E]
    const int*   dst  = (const int*)  d_in[2];   // [E]
    // d_in[3] edge_types: unused
    const float* W1   = (const float*)d_in[4];   // [64,8,32]
    const float* al1  = (const float*)d_in[5];   // [8,32]
    const float* ar1  = (const float*)d_in[6];   // [8,32]
    const float* b1   = (const float*)d_in[7];   // [8,32]
    const float* W2   = (const float*)d_in[8];   // [256,1,1]
    const float* al2  = (const float*)d_in[9];   // [1,1]
    const float* ar2  = (const float*)d_in[10];  // [1,1]
    const float* b2   = (const float*)d_in[11];  // [1,1]
    float* out = (float*)d_out;                  // [N,1]

    (void)in_sizes; (void)n_in; (void)out_size;

    // CSR build
    k_zero_deg<<<(N_NODES + 255) / 256, 256>>>();
    k_count<<<(N_EDGES / 4 + 255) / 256, 256>>>(dst);
    k_scan<<<1, 1024>>>();
    k_fill<<<(N_EDGES / 4 + 255) / 256, 256>>>(src, dst);

    // layer 1 (GEMM fused with el/er)
    k_gemm<<<(N_NODES + 15) / 16, 256>>>(x, W1, al1, ar1);
    k_agg1<<<(N_NODES + 7) / 8, 256>>>(b1, W2);

    // layer 2
    k_gat2<<<(N_NODES + 255) / 256, 256>>>(al2, ar2, b2, out);
}

// round 7
// speedup vs baseline: 1.3203x; 1.0910x over previous
#include <cuda_runtime.h>
#include <cuda_fp16.h>
#include <math.h>

// Problem constants (fixed by the reference)
#define N_NODES 50000
#define N_EDGES 800000
#define IN_F    64
#define HEADS   8
#define HID     32
#define CH      256          // HEADS*HID
#define NEG     0.2f

// ---------------- scratch (no cudaMalloc allowed) ----------------
__device__ __align__(16) __half g_feat1h[(size_t)N_NODES * CH];  // 25.6 MB fp16 gather table
__device__ float g_el1[N_NODES * HEADS];
__device__ float g_er1[N_NODES * HEADS];
__device__ float g_feat2[N_NODES];                // layer-2 per-node scalar feature
__device__ int   g_deg[N_NODES];
__device__ int   g_off[N_NODES];
__device__ int   g_rank[N_EDGES];                 // per-edge slot within its dst segment
__device__ int   g_csr_src[N_EDGES];
__device__ float g_Al[IN_F * HEADS];              // W-projected attention vectors
__device__ float g_Ar[IN_F * HEADS];

// ---------------- CSR construction ----------------
__global__ void k_zero_deg() {
    int i = blockIdx.x * blockDim.x + threadIdx.x;
    if (i < N_NODES) g_deg[i] = 0;
}

// count degrees AND record each edge's rank within its dst segment
__global__ void k_count(const int* __restrict__ dst) {
    int i = (blockIdx.x * blockDim.x + threadIdx.x) * 4;
    if (i + 3 < N_EDGES) {
        int4 d = *(const int4*)(dst + i);
        int4 r;
        r.x = atomicAdd(&g_deg[d.x], 1);
        r.y = atomicAdd(&g_deg[d.y], 1);
        r.z = atomicAdd(&g_deg[d.z], 1);
        r.w = atomicAdd(&g_deg[d.w], 1);
        *(int4*)(g_rank + i) = r;
    } else {
        for (int e = i; e < N_EDGES; ++e)
            g_rank[e] = atomicAdd(&g_deg[dst[e]], 1);
    }
}

// single-block exclusive scan over 50000 degrees -> offsets
__global__ void k_scan() {
    __shared__ int sums[1024];
    const int t = threadIdx.x;
    const int chunk = (N_NODES + 1023) / 1024;
    int begin = t * chunk;
    int end   = begin + chunk; if (end > N_NODES) end = N_NODES;
    int s = 0;
    for (int i = begin; i < end; ++i) s += g_deg[i];
    sums[t] = s;
    __syncthreads();
    for (int ofs = 1; ofs < 1024; ofs <<= 1) {
        int v = (t >= ofs) ? sums[t - ofs] : 0;
        __syncthreads();
        sums[t] += v;
        __syncthreads();
    }
    int run = (t == 0) ? 0 : sums[t - 1];
    for (int i = begin; i < end; ++i) {
        g_off[i] = run;
        run += g_deg[i];
    }
}

// non-atomic fill: slot = off[dst] + rank[e] is unique per edge
__global__ void k_fill(const int* __restrict__ src, const int* __restrict__ dst) {
    int i = (blockIdx.x * blockDim.x + threadIdx.x) * 4;
    if (i + 3 < N_EDGES) {
        int4 d = *(const int4*)(dst + i);
        int4 s = *(const int4*)(src + i);
        int4 r = *(const int4*)(g_rank + i);
        g_csr_src[g_off[d.x] + r.x] = s.x;
        g_csr_src[g_off[d.y] + r.y] = s.y;
        g_csr_src[g_off[d.z] + r.z] = s.z;
        g_csr_src[g_off[d.w] + r.w] = s.w;
    } else {
        for (int e = i; e < N_EDGES; ++e)
            g_csr_src[g_off[dst[e]] + g_rank[e]] = src[e];
    }
}

// ---------------- tiny projection: Al = W . al, Ar = W . ar ------------------
// el[n,h] = sum_o feat[n,h,o]*al[h,o] = sum_i x[n,i] * Al[i,h]
__global__ void k_proj(const float* __restrict__ W, const float* __restrict__ al,
                       const float* __restrict__ ar) {
    int t = threadIdx.x;            // 512 threads
    int i = t >> 3, h = t & 7;
    float sl = 0.f, sr = 0.f;
    #pragma unroll 8
    for (int o = 0; o < HID; ++o) {
        float w = W[i * CH + h * HID + o];
        sl = fmaf(w, al[h * HID + o], sl);
        sr = fmaf(w, ar[h * HID + o], sr);
    }
    g_Al[i * 8 + h] = sl;
    g_Ar[i * 8 + h] = sr;
}

// ---------------- layer-1 GEMM + el/er (no shuffles) -------------------------
// 256 threads (one output channel each), 32 nodes per block.
// el/er computed per-thread as x-row dot Al/Ar column from smem.
__global__ void k_gemm(const float* __restrict__ x, const float* __restrict__ W) {
    __shared__ float xs[32][IN_F + 1];     // +1 pad: kills bank conflicts in el/er
    __shared__ float sAl[IN_F][8], sAr[IN_F][8];
    const int tid = threadIdx.x;
    const int n0 = blockIdx.x * 32;
    #pragma unroll
    for (int r = 0; r < 8; ++r) {
        int e = tid + r * 256;
        int n = e >> 6, i = e & 63;
        int node = n0 + n;
        xs[n][i] = (node < N_NODES) ? x[node * IN_F + i] : 0.f;
    }
    #pragma unroll
    for (int r = 0; r < 2; ++r) {
        int e = tid + r * 256;
        sAl[e >> 3][e & 7] = g_Al[e];
        sAr[e >> 3][e & 7] = g_Ar[e];
    }
    __syncthreads();

    float acc[32];
    #pragma unroll
    for (int n = 0; n < 32; ++n) acc[n] = 0.f;
    const int c = tid;
    #pragma unroll 4
    for (int i = 0; i < IN_F; ++i) {
        float w = W[i * CH + c];
        #pragma unroll
        for (int n = 0; n < 32; ++n) acc[n] = fmaf(xs[n][i], w, acc[n]);
    }
    #pragma unroll
    for (int n = 0; n < 32; ++n) {
        int node = n0 + n;
        if (node < N_NODES) g_feat1h[(size_t)node * CH + c] = __float2half_rn(acc[n]);
    }

    // el/er: thread t handles (node tid>>3, head tid&7): two 64-wide dots
    const int nn = tid >> 3, h = tid & 7;
    float sl = 0.f, sr = 0.f;
    #pragma unroll 8
    for (int i = 0; i < IN_F; ++i) {
        float xv = xs[nn][i];
        sl = fmaf(xv, sAl[i][h], sl);
        sr = fmaf(xv, sAr[i][h], sr);
    }
    int node = n0 + nn;
    if (node < N_NODES) {
        g_el1[node * 8 + h] = sl;
        g_er1[node * 8 + h] = sr;
    }
}

// ---------------- layer-1 aggregation (warp per dst, single pass) ------------
// Single-pass softmax (no max-shift: logits bounded far below exp overflow).
// Batch-4 gathers + cross-iteration index prefetch for MLP.
// lane l owns channels [l*8, l*8+8); head = l/4.
// epilogue fuses +b1, ReLU, layer-2 linear h.W2 -> g_feat2[n]
__global__ void k_agg1(const float* __restrict__ b1, const float* __restrict__ W2) {
    const int warp = threadIdx.x >> 5, l = threadIdx.x & 31;
    const int n = blockIdx.x * 8 + warp;
    if (n >= N_NODES) return;
    const int h = l >> 2;
    const float er = g_er1[n * 8 + h];
    const int start = g_off[n], cnt = g_deg[n];

    float s = 0.f;
    float acc[8];
    #pragma unroll
    for (int i = 0; i < 8; ++i) acc[i] = 0.f;

    const int co = l << 3;
    int k = 0;
    if (cnt >= 4) {
        int cur[4];
        #pragma unroll
        for (int j = 0; j < 4; ++j) cur[j] = g_csr_src[start + j];
        while (k + 4 <= cnt) {
            float e[4];
            #pragma unroll
            for (int j = 0; j < 4; ++j) e[j] = g_el1[cur[j] * 8 + h];
            uint4 r[4];
            #pragma unroll
            for (int j = 0; j < 4; ++j)
                r[j] = *reinterpret_cast<const uint4*>(g_feat1h + (size_t)cur[j] * CH + co);
            k += 4;
            const bool more = (k + 4 <= cnt);
            int nxt[4];
            if (more) {
                #pragma unroll
                for (int j = 0; j < 4; ++j) nxt[j] = g_csr_src[start + k + j];
            }
            float p[4];
            #pragma unroll
            for (int j = 0; j < 4; ++j) {
                float ej = e[j] + er;
                ej = (ej > 0.f) ? ej : NEG * ej;
                p[j] = __expf(ej);
            }
            s += (p[0] + p[1]) + (p[2] + p[3]);
            #pragma unroll
            for (int j = 0; j < 4; ++j) {
                float2 f0 = __half22float2(*reinterpret_cast<__half2*>(&r[j].x));
                float2 f1 = __half22float2(*reinterpret_cast<__half2*>(&r[j].y));
                float2 f2 = __half22float2(*reinterpret_cast<__half2*>(&r[j].z));
                float2 f3 = __half22float2(*reinterpret_cast<__half2*>(&r[j].w));
                acc[0] = fmaf(p[j], f0.x, acc[0]);
                acc[1] = fmaf(p[j], f0.y, acc[1]);
                acc[2] = fmaf(p[j], f1.x, acc[2]);
                acc[3] = fmaf(p[j], f1.y, acc[3]);
                acc[4] = fmaf(p[j], f2.x, acc[4]);
                acc[5] = fmaf(p[j], f2.y, acc[5]);
                acc[6] = fmaf(p[j], f3.x, acc[6]);
                acc[7] = fmaf(p[j], f3.y, acc[7]);
            }
            if (more) {
                #pragma unroll
                for (int j = 0; j < 4; ++j) cur[j] = nxt[j];
            }
        }
    }
    for (; k < cnt; ++k) {
        int sn = g_csr_src[start + k];
        float e = g_el1[sn * 8 + h] + er;
        e = (e > 0.f) ? e : NEG * e;
        float p = __expf(e);
        s += p;
        uint4 rr = *reinterpret_cast<const uint4*>(g_feat1h + (size_t)sn * CH + co);
        float2 f0 = __half22float2(*reinterpret_cast<__half2*>(&rr.x));
        float2 f1 = __half22float2(*reinterpret_cast<__half2*>(&rr.y));
        float2 f2 = __half22float2(*reinterpret_cast<__half2*>(&rr.z));
        float2 f3 = __half22float2(*reinterpret_cast<__half2*>(&rr.w));
        acc[0] = fmaf(p, f0.x, acc[0]);
        acc[1] = fmaf(p, f0.y, acc[1]);
        acc[2] = fmaf(p, f1.x, acc[2]);
        acc[3] = fmaf(p, f1.y, acc[3]);
        acc[4] = fmaf(p, f2.x, acc[4]);
        acc[5] = fmaf(p, f2.y, acc[5]);
        acc[6] = fmaf(p, f3.x, acc[6]);
        acc[7] = fmaf(p, f3.y, acc[7]);
    }

    // epilogue: coalesced 32B loads of b1/W2 slices for this lane
    float4 bv0 = *reinterpret_cast<const float4*>(b1 + co);
    float4 bv1 = *reinterpret_cast<const float4*>(b1 + co + 4);
    float4 wv0 = *reinterpret_cast<const float4*>(W2 + co);
    float4 wv1 = *reinterpret_cast<const float4*>(W2 + co + 4);
    const float bb[8] = {bv0.x, bv0.y, bv0.z, bv0.w, bv1.x, bv1.y, bv1.z, bv1.w};
    const float ww[8] = {wv0.x, wv0.y, wv0.z, wv0.w, wv1.x, wv1.y, wv1.z, wv1.w};
    float inv = (cnt > 0) ? 1.f / s : 0.f;
    float dot = 0.f;
    #pragma unroll
    for (int i = 0; i < 8; ++i) {
        float v = acc[i] * inv + bb[i];
        v = fmaxf(v, 0.f);
        dot = fmaf(v, ww[i], dot);
    }
    #pragma unroll
    for (int o = 16; o; o >>= 1) dot += __shfl_xor_sync(0xffffffffu, dot, o);
    if (l == 0) g_feat2[n] = dot;
}

// ---------------- layer-2 aggregation + sigmoid (thread per dst) -------------
__global__ void k_gat2(const float* __restrict__ al2p, const float* __restrict__ ar2p,
                       const float* __restrict__ b2p, float* __restrict__ out) {
    int n = blockIdx.x * blockDim.x + threadIdx.x;
    if (n >= N_NODES) return;
    const float al2 = al2p[0], ar2 = ar2p[0], b2 = b2p[0];
    const float er = g_feat2[n] * ar2;
    const int start = g_off[n], cnt = g_deg[n];
    float s = 0.f, acc = 0.f;
    int k = 0;
    if (cnt >= 4) {
        int cur[4];
        #pragma unroll
        for (int j = 0; j < 4; ++j) cur[j] = g_csr_src[start + j];
        while (k + 4 <= cnt) {
            float f[4];
            #pragma unroll
            for (int j = 0; j < 4; ++j) f[j] = g_feat2[cur[j]];
            k += 4;
            const bool more = (k + 4 <= cnt);
            int nxt[4];
            if (more) {
                #pragma unroll
                for (int j = 0; j < 4; ++j) nxt[j] = g_csr_src[start + k + j];
            }
            #pragma unroll
            for (int j = 0; j < 4; ++j) {
                float e = f[j] * al2 + er;
                e = (e > 0.f) ? e : NEG * e;
                float p = __expf(e);
                s += p;
                acc = fmaf(p, f[j], acc);
            }
            if (more) {
                #pragma unroll
                for (int j = 0; j < 4; ++j) cur[j] = nxt[j];
            }
        }
    }
    for (; k < cnt; ++k) {
        float fs = g_feat2[g_csr_src[start + k]];
        float e = fs * al2 + er;
        e = (e > 0.f) ? e : NEG * e;
        float p = __expf(e);
        s += p;
        acc = fmaf(p, fs, acc);
    }
    float r = (cnt > 0) ? (acc / s + b2) : b2;
    out[n] = 1.f / (1.f + __expf(-r));
}

// ---------------- launch ----------------
extern "C" void kernel_launch(void* const* d_in, const int* in_sizes, int n_in,
                              void* d_out, int out_size) {
    const float* x    = (const float*)d_in[0];   // [N,64]
    const int*   src  = (const int*)  d_in[1];   // [E]
    const int*   dst  = (const int*)  d_in[2];   // [E]
    // d_in[3] edge_types: unused
    const float* W1   = (const float*)d_in[4];   // [64,8,32]
    const float* al1  = (const float*)d_in[5];   // [8,32]
    const float* ar1  = (const float*)d_in[6];   // [8,32]
    const float* b1   = (const float*)d_in[7];   // [8,32]
    const float* W2   = (const float*)d_in[8];   // [256,1,1]
    const float* al2  = (const float*)d_in[9];   // [1,1]
    const float* ar2  = (const float*)d_in[10];  // [1,1]
    const float* b2   = (const float*)d_in[11];  // [1,1]
    float* out = (float*)d_out;                  // [N,1]

    (void)in_sizes; (void)n_in; (void)out_size;

    // CSR build
    k_zero_deg<<<(N_NODES + 255) / 256, 256>>>();
    k_count<<<(N_EDGES / 4 + 255) / 256, 256>>>(dst);
    k_scan<<<1, 1024>>>();
    k_fill<<<(N_EDGES / 4 + 255) / 256, 256>>>(src, dst);

    // layer 1
    k_proj<<<1, 512>>>(W1, al1, ar1);
    k_gemm<<<(N_NODES + 31) / 32, 256>>>(x, W1);
    k_agg1<<<(N_NODES + 7) / 8, 256>>>(b1, W2);

    // layer 2
    k_gat2<<<(N_NODES + 255) / 256, 256>>>(al2, ar2, b2, out);
}

// round 8
// speedup vs baseline: 1.3377x; 1.0131x over previous
#include <cuda_runtime.h>
#include <cuda_fp16.h>
#include <math.h>

// Problem constants (fixed by the reference)
#define N_NODES 50000
#define N_EDGES 800000
#define IN_F    64
#define HEADS   8
#define HID     32
#define CH      256          // HEADS*HID
#define NEG     0.2f

// ---------------- scratch (no cudaMalloc allowed) ----------------
__device__ __align__(16) __half g_feat1h[(size_t)N_NODES * CH];  // 25.6 MB fp16 gather table
__device__ float g_el1[N_NODES * HEADS];
__device__ float g_er1[N_NODES * HEADS];
__device__ float g_feat2[N_NODES];                // layer-2 per-node scalar feature
__device__ int   g_deg[N_NODES];
__device__ int   g_off[N_NODES];
__device__ int   g_rank[N_EDGES];                 // per-edge slot within its dst segment
__device__ int   g_csr_src[N_EDGES];
__device__ float g_Al[IN_F * HEADS];              // W-projected attention vectors
__device__ float g_Ar[IN_F * HEADS];

// ---------------- CSR construction ----------------
__global__ void k_zero_deg() {
    int i = blockIdx.x * blockDim.x + threadIdx.x;
    if (i < N_NODES) g_deg[i] = 0;
}

// count degrees AND record each edge's rank within its dst segment
__global__ void k_count(const int* __restrict__ dst) {
    int i = (blockIdx.x * blockDim.x + threadIdx.x) * 4;
    if (i + 3 < N_EDGES) {
        int4 d = *(const int4*)(dst + i);
        int4 r;
        r.x = atomicAdd(&g_deg[d.x], 1);
        r.y = atomicAdd(&g_deg[d.y], 1);
        r.z = atomicAdd(&g_deg[d.z], 1);
        r.w = atomicAdd(&g_deg[d.w], 1);
        *(int4*)(g_rank + i) = r;
    } else {
        for (int e = i; e < N_EDGES; ++e)
            g_rank[e] = atomicAdd(&g_deg[dst[e]], 1);
    }
}

// single-block exclusive scan over 50000 degrees -> offsets
__global__ void k_scan() {
    __shared__ int sums[1024];
    const int t = threadIdx.x;
    const int chunk = (N_NODES + 1023) / 1024;
    int begin = t * chunk;
    int end   = begin + chunk; if (end > N_NODES) end = N_NODES;
    int s = 0;
    for (int i = begin; i < end; ++i) s += g_deg[i];
    sums[t] = s;
    __syncthreads();
    for (int ofs = 1; ofs < 1024; ofs <<= 1) {
        int v = (t >= ofs) ? sums[t - ofs] : 0;
        __syncthreads();
        sums[t] += v;
        __syncthreads();
    }
    int run = (t == 0) ? 0 : sums[t - 1];
    for (int i = begin; i < end; ++i) {
        g_off[i] = run;
        run += g_deg[i];
    }
}

// non-atomic fill: slot = off[dst] + rank[e] is unique per edge
__global__ void k_fill(const int* __restrict__ src, const int* __restrict__ dst) {
    int i = (blockIdx.x * blockDim.x + threadIdx.x) * 4;
    if (i + 3 < N_EDGES) {
        int4 d = *(const int4*)(dst + i);
        int4 s = *(const int4*)(src + i);
        int4 r = *(const int4*)(g_rank + i);
        g_csr_src[g_off[d.x] + r.x] = s.x;
        g_csr_src[g_off[d.y] + r.y] = s.y;
        g_csr_src[g_off[d.z] + r.z] = s.z;
        g_csr_src[g_off[d.w] + r.w] = s.w;
    } else {
        for (int e = i; e < N_EDGES; ++e)
            g_csr_src[g_off[dst[e]] + g_rank[e]] = src[e];
    }
}

// ---------------- tiny projection: Al = W . al, Ar = W . ar ------------------
// el[n,h] = sum_o feat[n,h,o]*al[h,o] = sum_i x[n,i] * Al[i,h]
__global__ void k_proj(const float* __restrict__ W, const float* __restrict__ al,
                       const float* __restrict__ ar) {
    int t = threadIdx.x;            // 512 threads
    int i = t >> 3, h = t & 7;
    float sl = 0.f, sr = 0.f;
    #pragma unroll 8
    for (int o = 0; o < HID; ++o) {
        float w = W[i * CH + h * HID + o];
        sl = fmaf(w, al[h * HID + o], sl);
        sr = fmaf(w, ar[h * HID + o], sr);
    }
    g_Al[i * 8 + h] = sl;
    g_Ar[i * 8 + h] = sr;
}

// ---------------- layer-1 GEMM + el/er (LDS.128, W column in registers) ------
// 256 threads (one output channel each), 32 nodes per block, n-outer loop:
// 4 FMA per LDS.128 instead of 1 FMA per LDS.32.
__global__ void k_gemm(const float* __restrict__ x, const float* __restrict__ W) {
    __shared__ float xs[32][IN_F + 4];     // row stride 272B (16B aligned), pad avoids conflicts
    __shared__ float sAl[IN_F][8], sAr[IN_F][8];
    const int tid = threadIdx.x;
    const int n0 = blockIdx.x * 32;
    // load x rows as float4 (512 float4 per block, 2 per thread)
    #pragma unroll
    for (int r = 0; r < 2; ++r) {
        int e = tid + r * 256;             // 0..511 : node = e>>4, i4 = e&15
        int n = e >> 4, i4 = e & 15;
        int node = n0 + n;
        float4 v = (node < N_NODES) ? ((const float4*)(x + (size_t)node * IN_F))[i4]
                                    : make_float4(0.f, 0.f, 0.f, 0.f);
        *(float4*)&xs[n][i4 * 4] = v;
    }
    #pragma unroll
    for (int r = 0; r < 2; ++r) {
        int e = tid + r * 256;
        sAl[e >> 3][e & 7] = g_Al[e];
        sAr[e >> 3][e & 7] = g_Ar[e];
    }
    __syncthreads();

    const int c = tid;
    float wreg[IN_F];
    #pragma unroll
    for (int i = 0; i < IN_F; ++i) wreg[i] = W[i * CH + c];

    #pragma unroll 4
    for (int n = 0; n < 32; ++n) {
        const float4* xr = (const float4*)xs[n];
        float a = 0.f;
        #pragma unroll
        for (int i4 = 0; i4 < 16; ++i4) {
            float4 xv = xr[i4];
            a = fmaf(xv.x, wreg[4 * i4 + 0], a);
            a = fmaf(xv.y, wreg[4 * i4 + 1], a);
            a = fmaf(xv.z, wreg[4 * i4 + 2], a);
            a = fmaf(xv.w, wreg[4 * i4 + 3], a);
        }
        int node = n0 + n;
        if (node < N_NODES) g_feat1h[(size_t)node * CH + c] = __float2half_rn(a);
    }

    // el/er: thread t handles (node tid>>3, head tid&7): two 64-wide dots
    const int nn = tid >> 3, h = tid & 7;
    const float4* xr = (const float4*)xs[nn];
    float sl = 0.f, sr = 0.f;
    #pragma unroll
    for (int i4 = 0; i4 < 16; ++i4) {
        float4 xv = xr[i4];
        sl = fmaf(xv.x, sAl[4 * i4 + 0][h], sl); sr = fmaf(xv.x, sAr[4 * i4 + 0][h], sr);
        sl = fmaf(xv.y, sAl[4 * i4 + 1][h], sl); sr = fmaf(xv.y, sAr[4 * i4 + 1][h], sr);
        sl = fmaf(xv.z, sAl[4 * i4 + 2][h], sl); sr = fmaf(xv.z, sAr[4 * i4 + 2][h], sr);
        sl = fmaf(xv.w, sAl[4 * i4 + 3][h], sl); sr = fmaf(xv.w, sAr[4 * i4 + 3][h], sr);
    }
    int node = n0 + nn;
    if (node < N_NODES) {
        g_el1[node * 8 + h] = sl;
        g_er1[node * 8 + h] = sr;
    }
}

// ---------------- layer-1 aggregation (warp per dst, batch-8 + prefetch) -----
// Single-pass softmax (no max-shift: logits bounded far below exp overflow).
// lane l owns channels [l*8, l*8+8); head = l/4.
// epilogue fuses +b1, ReLU, layer-2 linear h.W2 -> g_feat2[n]
__global__ void k_agg1(const float* __restrict__ b1, const float* __restrict__ W2) {
    const int warp = threadIdx.x >> 5, l = threadIdx.x & 31;
    const int n = blockIdx.x * 8 + warp;
    if (n >= N_NODES) return;
    const int h = l >> 2;
    const float er = g_er1[n * 8 + h];
    const int start = g_off[n], cnt = g_deg[n];

    float s = 0.f;
    float acc[8];
    #pragma unroll
    for (int i = 0; i < 8; ++i) acc[i] = 0.f;

    const int co = l << 3;
    int k = 0;
    if (cnt >= 8) {
        int cur[8];
        #pragma unroll
        for (int j = 0; j < 8; ++j) cur[j] = g_csr_src[start + j];
        while (k + 8 <= cnt) {
            float e[8];
            #pragma unroll
            for (int j = 0; j < 8; ++j) e[j] = g_el1[cur[j] * 8 + h];
            uint4 r[8];
            #pragma unroll
            for (int j = 0; j < 8; ++j)
                r[j] = *reinterpret_cast<const uint4*>(g_feat1h + (size_t)cur[j] * CH + co);
            k += 8;
            const bool more = (k + 8 <= cnt);
            if (more) {
                #pragma unroll
                for (int j = 0; j < 8; ++j) cur[j] = g_csr_src[start + k + j];
            }
            float p[8];
            #pragma unroll
            for (int j = 0; j < 8; ++j) {
                float ej = e[j] + er;
                ej = (ej > 0.f) ? ej : NEG * ej;
                p[j] = __expf(ej);
            }
            #pragma unroll
            for (int j = 0; j < 8; ++j) s += p[j];
            #pragma unroll
            for (int j = 0; j < 8; ++j) {
                float2 f0 = __half22float2(*reinterpret_cast<__half2*>(&r[j].x));
                float2 f1 = __half22float2(*reinterpret_cast<__half2*>(&r[j].y));
                float2 f2 = __half22float2(*reinterpret_cast<__half2*>(&r[j].z));
                float2 f3 = __half22float2(*reinterpret_cast<__half2*>(&r[j].w));
                acc[0] = fmaf(p[j], f0.x, acc[0]);
                acc[1] = fmaf(p[j], f0.y, acc[1]);
                acc[2] = fmaf(p[j], f1.x, acc[2]);
                acc[3] = fmaf(p[j], f1.y, acc[3]);
                acc[4] = fmaf(p[j], f2.x, acc[4]);
                acc[5] = fmaf(p[j], f2.y, acc[5]);
                acc[6] = fmaf(p[j], f3.x, acc[6]);
                acc[7] = fmaf(p[j], f3.y, acc[7]);
            }
        }
    }
    for (; k < cnt; ++k) {
        int sn = g_csr_src[start + k];
        float e = g_el1[sn * 8 + h] + er;
        e = (e > 0.f) ? e : NEG * e;
        float p = __expf(e);
        s += p;
        uint4 rr = *reinterpret_cast<const uint4*>(g_feat1h + (size_t)sn * CH + co);
        float2 f0 = __half22float2(*reinterpret_cast<__half2*>(&rr.x));
        float2 f1 = __half22float2(*reinterpret_cast<__half2*>(&rr.y));
        float2 f2 = __half22float2(*reinterpret_cast<__half2*>(&rr.z));
        float2 f3 = __half22float2(*reinterpret_cast<__half2*>(&rr.w));
        acc[0] = fmaf(p, f0.x, acc[0]);
        acc[1] = fmaf(p, f0.y, acc[1]);
        acc[2] = fmaf(p, f1.x, acc[2]);
        acc[3] = fmaf(p, f1.y, acc[3]);
        acc[4] = fmaf(p, f2.x, acc[4]);
        acc[5] = fmaf(p, f2.y, acc[5]);
        acc[6] = fmaf(p, f3.x, acc[6]);
        acc[7] = fmaf(p, f3.y, acc[7]);
    }

    // epilogue: coalesced 32B loads of b1/W2 slices for this lane
    float4 bv0 = *reinterpret_cast<const float4*>(b1 + co);
    float4 bv1 = *reinterpret_cast<const float4*>(b1 + co + 4);
    float4 wv0 = *reinterpret_cast<const float4*>(W2 + co);
    float4 wv1 = *reinterpret_cast<const float4*>(W2 + co + 4);
    const float bb[8] = {bv0.x, bv0.y, bv0.z, bv0.w, bv1.x, bv1.y, bv1.z, bv1.w};
    const float ww[8] = {wv0.x, wv0.y, wv0.z, wv0.w, wv1.x, wv1.y, wv1.z, wv1.w};
    float inv = (cnt > 0) ? 1.f / s : 0.f;
    float dot = 0.f;
    #pragma unroll
    for (int i = 0; i < 8; ++i) {
        float v = acc[i] * inv + bb[i];
        v = fmaxf(v, 0.f);
        dot = fmaf(v, ww[i], dot);
    }
    #pragma unroll
    for (int o = 16; o; o >>= 1) dot += __shfl_xor_sync(0xffffffffu, dot, o);
    if (l == 0) g_feat2[n] = dot;
}

// ---------------- layer-2 aggregation + sigmoid (thread per dst) -------------
__global__ void k_gat2(const float* __restrict__ al2p, const float* __restrict__ ar2p,
                       const float* __restrict__ b2p, float* __restrict__ out) {
    int n = blockIdx.x * blockDim.x + threadIdx.x;
    if (n >= N_NODES) return;
    const float al2 = al2p[0], ar2 = ar2p[0], b2 = b2p[0];
    const float er = g_feat2[n] * ar2;
    const int start = g_off[n], cnt = g_deg[n];
    float s = 0.f, acc = 0.f;
    int k = 0;
    if (cnt >= 4) {
        int cur[4];
        #pragma unroll
        for (int j = 0; j < 4; ++j) cur[j] = g_csr_src[start + j];
        while (k + 4 <= cnt) {
            float f[4];
            #pragma unroll
            for (int j = 0; j < 4; ++j) f[j] = g_feat2[cur[j]];
            k += 4;
            const bool more = (k + 4 <= cnt);
            int nxt[4];
            if (more) {
                #pragma unroll
                for (int j = 0; j < 4; ++j) nxt[j] = g_csr_src[start + k + j];
            }
            #pragma unroll
            for (int j = 0; j < 4; ++j) {
                float e = f[j] * al2 + er;
                e = (e > 0.f) ? e : NEG * e;
                float p = __expf(e);
                s += p;
                acc = fmaf(p, f[j], acc);
            }
            if (more) {
                #pragma unroll
                for (int j = 0; j < 4; ++j) cur[j] = nxt[j];
            }
        }
    }
    for (; k < cnt; ++k) {
        float fs = g_feat2[g_csr_src[start + k]];
        float e = fs * al2 + er;
        e = (e > 0.f) ? e : NEG * e;
        float p = __expf(e);
        s += p;
        acc = fmaf(p, fs, acc);
    }
    float r = (cnt > 0) ? (acc / s + b2) : b2;
    out[n] = 1.f / (1.f + __expf(-r));
}

// ---------------- launch ----------------
extern "C" void kernel_launch(void* const* d_in, const int* in_sizes, int n_in,
                              void* d_out, int out_size) {
    const float* x    = (const float*)d_in[0];   // [N,64]
    const int*   src  = (const int*)  d_in[1];   // [E]
    const int*   dst  = (const int*)  d_in[2];   // [E]
    // d_in[3] edge_types: unused
    const float* W1   = (const float*)d_in[4];   // [64,8,32]
    const float* al1  = (const float*)d_in[5];   // [8,32]
    const float* ar1  = (const float*)d_in[6];   // [8,32]
    const float* b1   = (const float*)d_in[7];   // [8,32]
    const float* W2   = (const float*)d_in[8];   // [256,1,1]
    const float* al2  = (const float*)d_in[9];   // [1,1]
    const float* ar2  = (const float*)d_in[10];  // [1,1]
    const float* b2   = (const float*)d_in[11];  // [1,1]
    float* out = (float*)d_out;                  // [N,1]

    (void)in_sizes; (void)n_in; (void)out_size;

    // CSR build
    k_zero_deg<<<(N_NODES + 255) / 256, 256>>>();
    k_count<<<(N_EDGES / 4 + 255) / 256, 256>>>(dst);
    k_scan<<<1, 1024>>>();
    k_fill<<<(N_EDGES / 4 + 255) / 256, 256>>>(src, dst);

    // layer 1
    k_proj<<<1, 512>>>(W1, al1, ar1);
    k_gemm<<<(N_NODES + 31) / 32, 256>>>(x, W1);
    k_agg1<<<(N_NODES + 7) / 8, 256>>>(b1, W2);

    // layer 2
    k_gat2<<<(N_NODES + 255) / 256, 256>>>(al2, ar2, b2, out);
}